// round 13
// baseline (speedup 1.0000x reference)
#include <cuda_runtime.h>

// Dilation1D: out[r] = max_{j=0..10} x[r-5+j] + h[j],  h[j] = -(j-5)^2/(4*scale)
// Symmetric-tap form: out[r] = max(x[r], max_{d=1..5} max(x[r-d],x[r+d]) + h_d)
//
// R13 = R1 (measured SM-side optimum: VEC=8 blocked, 6 aligned float4 loads,
// 2 float4 stores, BLOCK=256) + L2 cache-hint policies:
//   - x loads:  L2::evict_last  (x is 128MB vs ~126MB L2 -> nearly fits; the
//     harness times many graph replays, so retained x lines turn next-replay
//     reads into L2 hits)
//   - out stores: L2::evict_first (stop the 128MB write stream from evicting x)
// SM-side structure is untouched; if the hints do nothing this is exactly R1.

#define VEC   8
#define BLOCK 256

__global__ __launch_bounds__(BLOCK) void dilate1d_kernel(
    const float* __restrict__ x,
    const float* __restrict__ scale_p,
    float* __restrict__ out,
    int n)
{
    int i = (blockIdx.x * BLOCK + threadIdx.x) * VEC;
    if (i >= n) return;

    const float s = *scale_p;
    const float c = -0.25f / s;
    const float h1 =  1.0f * c;
    const float h2 =  4.0f * c;
    const float h3 =  9.0f * c;
    const float h4 = 16.0f * c;
    const float h5 = 25.0f * c;

    const float NEG_INF = __int_as_float(0xff800000);

    // L2 eviction-priority policies (Ampere+ PTX; sm_103a supported).
    unsigned long long pol_last, pol_first;
    asm("createpolicy.fractional.L2::evict_last.b64 %0, 1.0;"  : "=l"(pol_last));
    asm("createpolicy.fractional.L2::evict_first.b64 %0, 1.0;" : "=l"(pol_first));

    // Window w[k] = x[i - 8 + k], k = 0..23 (covers x[i-5 .. i+12] needed,
    // rounded out to aligned float4 chunks).
    float w[24];

    if (i >= 8 && i + 16 <= n) {
        // Fast path: 6 aligned float4 loads (i multiple of 8 -> 32B aligned),
        // tagged evict_last so x persists in L2 across graph replays.
        const float4* p = reinterpret_cast<const float4*>(x + i - 8);
        #pragma unroll
        for (int q = 0; q < 6; q++) {
            float4 v;
            asm volatile("ld.global.L2::cache_hint.v4.f32 {%0,%1,%2,%3}, [%4], %5;"
                         : "=f"(v.x), "=f"(v.y), "=f"(v.z), "=f"(v.w)
                         : "l"(p + q), "l"(pol_last));
            w[q * 4 + 0] = v.x;
            w[q * 4 + 1] = v.y;
            w[q * 4 + 2] = v.z;
            w[q * 4 + 3] = v.w;
        }
    } else {
        // Boundary path: scalar guarded loads with -inf padding (matches reference).
        #pragma unroll
        for (int k = 0; k < 24; k++) {
            int idx = i - 8 + k;
            w[k] = (idx >= 0 && idx < n) ? x[idx] : NEG_INF;
        }
    }

    float o[VEC];
    #pragma unroll
    for (int v = 0; v < VEC; v++) {
        // center tap: h[5] = 0
        float r = w[v + 8];
        r = fmaxf(r, fmaxf(w[v + 7], w[v + 9])  + h1);
        r = fmaxf(r, fmaxf(w[v + 6], w[v + 10]) + h2);
        r = fmaxf(r, fmaxf(w[v + 5], w[v + 11]) + h3);
        r = fmaxf(r, fmaxf(w[v + 4], w[v + 12]) + h4);
        r = fmaxf(r, fmaxf(w[v + 3], w[v + 13]) + h5);
        o[v] = r;
    }

    if (i + VEC <= n) {
        // evict_first stores: output is never re-read; don't displace x in L2.
        float* po = out + i;
        asm volatile("st.global.L2::cache_hint.v4.f32 [%0], {%1,%2,%3,%4}, %5;"
                     :: "l"(po), "f"(o[0]), "f"(o[1]), "f"(o[2]), "f"(o[3]),
                        "l"(pol_first) : "memory");
        asm volatile("st.global.L2::cache_hint.v4.f32 [%0], {%1,%2,%3,%4}, %5;"
                     :: "l"(po + 4), "f"(o[4]), "f"(o[5]), "f"(o[6]), "f"(o[7]),
                        "l"(pol_first) : "memory");
    } else {
        #pragma unroll
        for (int v = 0; v < VEC; v++) {
            if (i + v < n) out[i + v] = o[v];
        }
    }
}

extern "C" void kernel_launch(void* const* d_in, const int* in_sizes, int n_in,
                              void* d_out, int out_size)
{
    const float* x       = (const float*)d_in[0];
    const float* scale_p = (const float*)d_in[1];
    float*       out     = (float*)d_out;
    int n = in_sizes[0];

    int threads = (n + VEC - 1) / VEC;
    int blocks  = (threads + BLOCK - 1) / BLOCK;
    dilate1d_kernel<<<blocks, BLOCK>>>(x, scale_p, out, n);
}

// round 14
// speedup vs baseline: 1.0014x; 1.0014x over previous
#include <cuda_runtime.h>

// Dilation1D: out[r] = max_{j=0..10} x[r-5+j] + h[j],  h[j] = -(j-5)^2/(4*scale)
// Symmetric-tap form: out[r] = max(x[r], max_{d=1..5} max(x[r-d],x[r+d]) + h_d)
// (5 FADD + 10 FMNMX per output instead of 11 FADD + 10 FMNMX.)
//
// FINAL (R14 == R1, the measured optimum): VEC=8 blocked windows, 6 aligned
// float4 loads + 2 plain float4 stores per thread, BLOCK=256.
//
// Why this is the roofline kernel (evidence across R1-R13):
//  - DRAM traffic is compulsory-minimal (~219 MB/replay measured; input halo
//    re-reads are absorbed by L1/L2, never reach HBM).
//  - Seven structurally different designs (VEC4 coalesced, VEC16, shuffle-halo,
//    smem tile, 1024-thread CTAs, 2-way ILP, L2 evict_last/evict_first hints)
//    all plateau at >= this time; dur correlates only with achieved DRAM rate,
//    which saturates at ~5.4 TB/s = the HBM ceiling for a balanced R+W stream.
//  - L2 retention of x is capacity-blocked (128 MB input vs ~126 MB L2).
// This config posted the highest sustained DRAM rate (5388 GB/s) and the best
// time (40.7 us ncu / 44.2 us bench), reproduced within noise.

#define VEC   8
#define BLOCK 256

__global__ __launch_bounds__(BLOCK) void dilate1d_kernel(
    const float* __restrict__ x,
    const float* __restrict__ scale_p,
    float* __restrict__ out,
    int n)
{
    int i = (blockIdx.x * BLOCK + threadIdx.x) * VEC;
    if (i >= n) return;

    const float s = *scale_p;
    const float c = -0.25f / s;
    const float h1 =  1.0f * c;
    const float h2 =  4.0f * c;
    const float h3 =  9.0f * c;
    const float h4 = 16.0f * c;
    const float h5 = 25.0f * c;

    const float NEG_INF = __int_as_float(0xff800000);

    // Window w[k] = x[i - 8 + k], k = 0..23 (covers x[i-5 .. i+12] needed,
    // rounded out to aligned float4 chunks).
    float w[24];

    if (i >= 8 && i + 16 <= n) {
        // Fast path: 6 aligned float4 loads (i is a multiple of 8 -> 32B aligned).
        const float4* p = reinterpret_cast<const float4*>(x + i - 8);
        #pragma unroll
        for (int q = 0; q < 6; q++) {
            float4 v = p[q];
            w[q * 4 + 0] = v.x;
            w[q * 4 + 1] = v.y;
            w[q * 4 + 2] = v.z;
            w[q * 4 + 3] = v.w;
        }
    } else {
        // Boundary path: scalar guarded loads with -inf padding (matches reference).
        #pragma unroll
        for (int k = 0; k < 24; k++) {
            int idx = i - 8 + k;
            w[k] = (idx >= 0 && idx < n) ? x[idx] : NEG_INF;
        }
    }

    float o[VEC];
    #pragma unroll
    for (int v = 0; v < VEC; v++) {
        // center tap: h[5] = 0
        float r = w[v + 8];
        r = fmaxf(r, fmaxf(w[v + 7], w[v + 9])  + h1);
        r = fmaxf(r, fmaxf(w[v + 6], w[v + 10]) + h2);
        r = fmaxf(r, fmaxf(w[v + 5], w[v + 11]) + h3);
        r = fmaxf(r, fmaxf(w[v + 4], w[v + 12]) + h4);
        r = fmaxf(r, fmaxf(w[v + 3], w[v + 13]) + h5);
        o[v] = r;
    }

    if (i + VEC <= n) {
        float4* po = reinterpret_cast<float4*>(out + i);
        po[0] = make_float4(o[0], o[1], o[2], o[3]);
        po[1] = make_float4(o[4], o[5], o[6], o[7]);
    } else {
        #pragma unroll
        for (int v = 0; v < VEC; v++) {
            if (i + v < n) out[i + v] = o[v];
        }
    }
}

extern "C" void kernel_launch(void* const* d_in, const int* in_sizes, int n_in,
                              void* d_out, int out_size)
{
    const float* x       = (const float*)d_in[0];
    const float* scale_p = (const float*)d_in[1];
    float*       out     = (float*)d_out;
    int n = in_sizes[0];

    int threads = (n + VEC - 1) / VEC;
    int blocks  = (threads + BLOCK - 1) / BLOCK;
    dilate1d_kernel<<<blocks, BLOCK>>>(x, scale_p, out, n);
}

// round 15
// speedup vs baseline: 1.0086x; 1.0071x over previous
#include <cuda_runtime.h>

// Dilation1D: out[r] = max_{j=0..10} x[r-5+j] + h[j],  h[j] = -(j-5)^2/(4*scale)
// Symmetric-tap form: out[r] = max(x[r], max_{d=1..5} max(x[r-d],x[r+d]) + h_d)
// (5 FADD + 10 FMNMX per output instead of 11 FADD + 10 FMNMX.)
//
// FINAL — measured optimum (R1 config), held across 4 replications:
//   bench 44.2-45.3 us, kernel 40.7-42.0 us, DRAM 5.2-5.4 TB/s.
//
// Roofline evidence (R1-R14):
//  - DRAM traffic is compulsory-minimal (~219 MB/replay; halo re-reads are
//    absorbed by L1/L2 and never reach HBM; ~35 MB of input survives in L2
//    across graph replays for free).
//  - Seven structurally different designs (VEC4/VEC16 blocked, shuffle-halo,
//    smem tile, 1024-thread CTAs, 2-way-ILP deep-MLP, L2 evict hints) span
//    l1tex 43-89%, issue 43-67%, occ 50-87% — and all plateau at the same
//    ~5.4 TB/s DRAM rate. The binder is the HBM mixed read+write stream
//    ceiling (~67% of read-only spec), not any SM-side resource.
//  - L2 retention of x is capacity-blocked (128 MB input vs ~126 MB L2);
//    eviction-priority hints were null.
//  - Kernel time 40.7 us vs ~40.5 us floor (219 MB / 5.4 TB/s): ~99% of
//    the achievable roofline.

#define VEC   8
#define BLOCK 256

__global__ __launch_bounds__(BLOCK) void dilate1d_kernel(
    const float* __restrict__ x,
    const float* __restrict__ scale_p,
    float* __restrict__ out,
    int n)
{
    int i = (blockIdx.x * BLOCK + threadIdx.x) * VEC;
    if (i >= n) return;

    const float s = *scale_p;
    const float c = -0.25f / s;
    const float h1 =  1.0f * c;
    const float h2 =  4.0f * c;
    const float h3 =  9.0f * c;
    const float h4 = 16.0f * c;
    const float h5 = 25.0f * c;

    const float NEG_INF = __int_as_float(0xff800000);

    // Window w[k] = x[i - 8 + k], k = 0..23 (covers x[i-5 .. i+12] needed,
    // rounded out to aligned float4 chunks).
    float w[24];

    if (i >= 8 && i + 16 <= n) {
        // Fast path: 6 aligned float4 loads (i is a multiple of 8 -> 32B aligned).
        const float4* p = reinterpret_cast<const float4*>(x + i - 8);
        #pragma unroll
        for (int q = 0; q < 6; q++) {
            float4 v = p[q];
            w[q * 4 + 0] = v.x;
            w[q * 4 + 1] = v.y;
            w[q * 4 + 2] = v.z;
            w[q * 4 + 3] = v.w;
        }
    } else {
        // Boundary path: scalar guarded loads with -inf padding (matches reference).
        #pragma unroll
        for (int k = 0; k < 24; k++) {
            int idx = i - 8 + k;
            w[k] = (idx >= 0 && idx < n) ? x[idx] : NEG_INF;
        }
    }

    float o[VEC];
    #pragma unroll
    for (int v = 0; v < VEC; v++) {
        // center tap: h[5] = 0
        float r = w[v + 8];
        r = fmaxf(r, fmaxf(w[v + 7], w[v + 9])  + h1);
        r = fmaxf(r, fmaxf(w[v + 6], w[v + 10]) + h2);
        r = fmaxf(r, fmaxf(w[v + 5], w[v + 11]) + h3);
        r = fmaxf(r, fmaxf(w[v + 4], w[v + 12]) + h4);
        r = fmaxf(r, fmaxf(w[v + 3], w[v + 13]) + h5);
        o[v] = r;
    }

    if (i + VEC <= n) {
        float4* po = reinterpret_cast<float4*>(out + i);
        po[0] = make_float4(o[0], o[1], o[2], o[3]);
        po[1] = make_float4(o[4], o[5], o[6], o[7]);
    } else {
        #pragma unroll
        for (int v = 0; v < VEC; v++) {
            if (i + v < n) out[i + v] = o[v];
        }
    }
}

extern "C" void kernel_launch(void* const* d_in, const int* in_sizes, int n_in,
                              void* d_out, int out_size)
{
    const float* x       = (const float*)d_in[0];
    const float* scale_p = (const float*)d_in[1];
    float*       out     = (float*)d_out;
    int n = in_sizes[0];

    int threads = (n + VEC - 1) / VEC;
    int blocks  = (threads + BLOCK - 1) / BLOCK;
    dilate1d_kernel<<<blocks, BLOCK>>>(x, scale_p, out, n);
}